// round 11
// baseline (speedup 1.0000x reference)
#include <cuda_runtime.h>

#define IN_DIM   128
#define EDGE_DIM 64
#define K1       192   // IN_DIM + EDGE_DIM
#define HID      256
#define OUT_DIM  128
#define N_EDGES_MAX 640000

// Scratch (runtime allocation forbidden; __device__ globals are the sanctioned path)
__device__ float g_h[(size_t)N_EDGES_MAX * HID];   // hidden activations [E, HID]
__device__ int   g_src[N_EDGES_MAX];
__device__ int   g_dst[N_EDGES_MAX];

// ---------------- packed f32x2 helpers (Blackwell FFMA2: 2x fp32 FMA tput) ---
__device__ __forceinline__ unsigned long long pack2(float x) {
    unsigned long long r;
    asm("mov.b64 %0, {%1, %1};" : "=l"(r) : "f"(x));
    return r;
}
__device__ __forceinline__ void fma2(unsigned long long& c,
                                     unsigned long long a,
                                     unsigned long long b) {
    asm("fma.rn.f32x2 %0, %1, %2, %0;" : "+l"(c) : "l"(a), "l"(b));
}
__device__ __forceinline__ void unpack2(unsigned long long c, float& lo, float& hi) {
    asm("mov.b64 {%0, %1}, %2;" : "=f"(lo), "=f"(hi) : "l"(c));
}

// ---------------- zero the output (poisoned to 0xAA by the harness) ----------
__global__ void zero_out_kernel(float* __restrict__ out, int n) {
    for (int i = blockIdx.x * blockDim.x + threadIdx.x; i < n;
         i += gridDim.x * blockDim.x)
        out[i] = 0.0f;
}

// =============================================================================
// Decode edge_index into int32 src/dst arrays, robust to the harness handing
// us int64 OR int32 data. Detection: interpret the first 64 entries as int64 —
// genuine int64 indices all lie in [0, n_nodes); int32 data read as int64
// packs a random upper word, so at least one value is out of range
// (miss probability ~ (1e-4)^64).
// =============================================================================
__global__ void decode_edges(const void* __restrict__ ei_raw, int E, int n_nodes) {
    const long long* e64 = (const long long*)ei_raw;
    const int*       e32 = (const int*)ei_raw;

    bool is64 = true;
#pragma unroll 1
    for (int i = 0; i < 64; i++) {
        long long v = e64[i];
        if (v < 0 || v >= (long long)n_nodes) { is64 = false; break; }
    }

    for (int e = blockIdx.x * blockDim.x + threadIdx.x; e < E;
         e += gridDim.x * blockDim.x) {
        if (is64) {
            g_src[e] = (int)e64[e];
            g_dst[e] = (int)e64[(long)E + e];
        } else {
            g_src[e] = e32[e];
            g_dst[e] = e32[E + e];
        }
    }
}

// =============================================================================
// Kernel 1: h[e, :] = relu( concat(x[src[e]], edge_attr[e]) @ W1^T + b1 )
//   Block tile 128 edges x 128 hid, K-tile 16, microtile 8x8, 256 threads.
//   grid = (E/128, HID/128)
// =============================================================================
__global__ __launch_bounds__(256, 2)
void gemm1_relu(const float* __restrict__ x,
                const float* __restrict__ ea,       // [E, EDGE_DIM]
                const float* __restrict__ W1,       // [HID, K1] row-major
                const float* __restrict__ b1)       // [HID]
{
    __shared__ float As[16][128];
    __shared__ float Bs[16][128];
    __shared__ int   s_src[128];

    const int tid  = threadIdx.x;
    const int eblk = blockIdx.x * 128;
    const int nblk = blockIdx.y * 128;

    if (tid < 128) s_src[tid] = g_src[eblk + tid];
    __syncthreads();

    const int tx = tid & 15;      // 0..15 -> column groups
    const int ty = tid >> 4;      // 0..15 -> row group (8 rows each)

    unsigned long long acc[8][4];
#pragma unroll
    for (int i = 0; i < 8; i++)
#pragma unroll
        for (int j = 0; j < 4; j++) acc[i][j] = 0ull;

#pragma unroll 1
    for (int kt = 0; kt < K1 / 16; kt++) {
        const int k0 = kt * 16;
        if (kt) __syncthreads();   // protect smem from previous compute

        // ---- load tiles: 512 float4 each, 2 per thread ----
#pragma unroll
        for (int r = 0; r < 2; r++) {
            int id = tid + r * 256;
            int m  = id >> 2;            // 0..127 (edge row / hid row)
            int k4 = (id & 3) << 2;      // 0,4,8,12
            float4 va;
            if (k0 < IN_DIM) {
                va = *(const float4*)(x + (long)s_src[m] * IN_DIM + k0 + k4);
            } else {
                va = *(const float4*)(ea + (long)(eblk + m) * EDGE_DIM + (k0 - IN_DIM) + k4);
            }
            As[k4 + 0][m] = va.x; As[k4 + 1][m] = va.y;
            As[k4 + 2][m] = va.z; As[k4 + 3][m] = va.w;

            float4 vb = *(const float4*)(W1 + (long)(nblk + m) * K1 + k0 + k4);
            Bs[k4 + 0][m] = vb.x; Bs[k4 + 1][m] = vb.y;
            Bs[k4 + 2][m] = vb.z; Bs[k4 + 3][m] = vb.w;
        }
        __syncthreads();

        // ---- 8x8 microtile FMA, packed f32x2 ----
#pragma unroll
        for (int k = 0; k < 16; k++) {
            unsigned long long ap[8], bp[4];
            const float* arow = &As[k][ty * 8];
#pragma unroll
            for (int i = 0; i < 8; i++) ap[i] = pack2(arow[i]);
            bp[0] = *(const unsigned long long*)&Bs[k][tx * 4];
            bp[1] = *(const unsigned long long*)&Bs[k][tx * 4 + 2];
            bp[2] = *(const unsigned long long*)&Bs[k][64 + tx * 4];
            bp[3] = *(const unsigned long long*)&Bs[k][64 + tx * 4 + 2];
#pragma unroll
            for (int i = 0; i < 8; i++)
#pragma unroll
                for (int j = 0; j < 4; j++) fma2(acc[i][j], ap[i], bp[j]);
        }
    }

    // ---- epilogue: bias + relu -> g_h ----
#pragma unroll
    for (int i = 0; i < 8; i++) {
        const long e = eblk + ty * 8 + i;
        float* hrow = g_h + e * HID + nblk;
#pragma unroll
        for (int j = 0; j < 4; j++) {
            int n = (j < 2) ? (tx * 4 + 2 * j) : (64 + tx * 4 + 2 * (j - 2));
            float lo, hi;
            unpack2(acc[i][j], lo, hi);
            lo = fmaxf(lo + b1[nblk + n], 0.0f);
            hi = fmaxf(hi + b1[nblk + n + 1], 0.0f);
            hrow[n]     = lo;
            hrow[n + 1] = hi;
        }
    }
}

// =============================================================================
// Kernel 2: msg[e, :] = h[e, :] @ W2^T + b2 ; atomicAdd into out[dst[e], :]
//   Block tile 128 edges x 128 out (full OUT_DIM), K = 256 in 16 steps.
//   grid = E/128
// =============================================================================
__global__ __launch_bounds__(256, 2)
void gemm2_scatter(const float* __restrict__ W2,      // [OUT, HID] row-major
                   const float* __restrict__ b2,      // [OUT]
                   float* __restrict__ out)           // [N, OUT]
{
    __shared__ float As[16][128];
    __shared__ float Bs[16][128];
    __shared__ int   s_dst[128];

    const int tid  = threadIdx.x;
    const int eblk = blockIdx.x * 128;

    if (tid < 128) s_dst[tid] = g_dst[eblk + tid];
    __syncthreads();

    const int tx = tid & 15;
    const int ty = tid >> 4;

    unsigned long long acc[8][4];
#pragma unroll
    for (int i = 0; i < 8; i++)
#pragma unroll
        for (int j = 0; j < 4; j++) acc[i][j] = 0ull;

#pragma unroll 1
    for (int kt = 0; kt < HID / 16; kt++) {
        const int k0 = kt * 16;
        if (kt) __syncthreads();

#pragma unroll
        for (int r = 0; r < 2; r++) {
            int id = tid + r * 256;
            int m  = id >> 2;
            int k4 = (id & 3) << 2;
            float4 va = *(const float4*)(g_h + (long)(eblk + m) * HID + k0 + k4);
            As[k4 + 0][m] = va.x; As[k4 + 1][m] = va.y;
            As[k4 + 2][m] = va.z; As[k4 + 3][m] = va.w;

            float4 vb = *(const float4*)(W2 + (long)m * HID + k0 + k4);
            Bs[k4 + 0][m] = vb.x; Bs[k4 + 1][m] = vb.y;
            Bs[k4 + 2][m] = vb.z; Bs[k4 + 3][m] = vb.w;
        }
        __syncthreads();

#pragma unroll
        for (int k = 0; k < 16; k++) {
            unsigned long long ap[8], bp[4];
            const float* arow = &As[k][ty * 8];
#pragma unroll
            for (int i = 0; i < 8; i++) ap[i] = pack2(arow[i]);
            bp[0] = *(const unsigned long long*)&Bs[k][tx * 4];
            bp[1] = *(const unsigned long long*)&Bs[k][tx * 4 + 2];
            bp[2] = *(const unsigned long long*)&Bs[k][64 + tx * 4];
            bp[3] = *(const unsigned long long*)&Bs[k][64 + tx * 4 + 2];
#pragma unroll
            for (int i = 0; i < 8; i++)
#pragma unroll
                for (int j = 0; j < 4; j++) fma2(acc[i][j], ap[i], bp[j]);
        }
    }

    // ---- epilogue: + b2, scatter-add by dst ----
#pragma unroll
    for (int i = 0; i < 8; i++) {
        float* orow = out + (long)s_dst[ty * 8 + i] * OUT_DIM;
#pragma unroll
        for (int j = 0; j < 4; j++) {
            int n = (j < 2) ? (tx * 4 + 2 * j) : (64 + tx * 4 + 2 * (j - 2));
            float lo, hi;
            unpack2(acc[i][j], lo, hi);
            atomicAdd(orow + n,     lo + b2[n]);
            atomicAdd(orow + n + 1, hi + b2[n + 1]);
        }
    }
}

// =============================================================================
extern "C" void kernel_launch(void* const* d_in, const int* in_sizes, int n_in,
                              void* d_out, int out_size)
{
    const float* x  = (const float*)d_in[0];
    const void*  ei = d_in[1];                 // int32 or int64 — decoded on device
    const float* ea = (const float*)d_in[2];
    const float* W1 = (const float*)d_in[3];
    const float* b1 = (const float*)d_in[4];
    const float* W2 = (const float*)d_in[5];
    const float* b2 = (const float*)d_in[6];
    float*       out = (float*)d_out;

    const int E       = in_sizes[2] / EDGE_DIM;   // 640000
    const int n_nodes = in_sizes[0] / IN_DIM;     // 10000

    int zblk = (out_size + 255) / 256;
    if (zblk > 2960) zblk = 2960;
    zero_out_kernel<<<zblk, 256>>>(out, out_size);

    decode_edges<<<592, 256>>>(ei, E, n_nodes);

    dim3 g1(E / 128, HID / 128);
    gemm1_relu<<<g1, 256>>>(x, ea, W1, b1);

    gemm2_scatter<<<E / 128, 256>>>(W2, b2, out);
}

// round 13
// speedup vs baseline: 1.5593x; 1.5593x over previous
#include <cuda_runtime.h>
#include <cstdint>

#define IN_DIM   128
#define EDGE_DIM 64
#define K1       192   // IN_DIM + EDGE_DIM
#define HID      256
#define OUT_DIM  128
#define N_NODES_MAX 10000
#define N_EDGES_MAX 640000

// ---------------- device scratch (runtime allocation forbidden) --------------
__device__ int   g_src[N_EDGES_MAX];
__device__ int   g_dst[N_EDGES_MAX];
__device__ float g_xh[(size_t)N_NODES_MAX * HID];   // x @ W1x^T + b1  (10.2 MB, L2-resident)

// ---------------- packed f32x2 helpers (Blackwell FFMA2: 2x fp32 FMA tput) ---
__device__ __forceinline__ unsigned long long pack2(float x) {
    unsigned long long r;
    asm("mov.b64 %0, {%1, %1};" : "=l"(r) : "f"(x));
    return r;
}
__device__ __forceinline__ void fma2(unsigned long long& c,
                                     unsigned long long a,
                                     unsigned long long b) {
    asm("fma.rn.f32x2 %0, %1, %2, %0;" : "+l"(c) : "l"(a), "l"(b));
}
__device__ __forceinline__ void unpack2(unsigned long long c, float& lo, float& hi) {
    asm("mov.b64 {%0, %1}, %2;" : "=f"(lo), "=f"(hi) : "l"(c));
}

// ---------------- zero the output (poisoned to 0xAA by the harness) ----------
__global__ void zero_out_kernel(float* __restrict__ out, int n) {
    for (int i = blockIdx.x * blockDim.x + threadIdx.x; i < n;
         i += gridDim.x * blockDim.x)
        out[i] = 0.0f;
}

// ---------------- decode edge_index (int64/int32 robust; validated R10) ------
__global__ void decode_edges(const void* __restrict__ ei_raw, int E, int n_nodes) {
    const long long* e64 = (const long long*)ei_raw;
    const int*       e32 = (const int*)ei_raw;
    bool is64 = true;
#pragma unroll 1
    for (int i = 0; i < 64; i++) {
        long long v = e64[i];
        if (v < 0 || v >= (long long)n_nodes) { is64 = false; break; }
    }
    for (int e = blockIdx.x * blockDim.x + threadIdx.x; e < E;
         e += gridDim.x * blockDim.x) {
        if (is64) { g_src[e] = (int)e64[e]; g_dst[e] = (int)e64[(long)E + e]; }
        else      { g_src[e] = e32[e];      g_dst[e] = e32[E + e]; }
    }
}

// =============================================================================
// Kernel A: g_xh[n, :] = x[n, :] @ W1x^T + b1   (W1x = W1[:, 0:128])
//   Tiny GEMM over nodes: grid (ceil(N/128), HID/128), tile 128x128, K=128.
// =============================================================================
__global__ __launch_bounds__(256, 2)
void xh_gemm(const float* __restrict__ x,
             const float* __restrict__ W1,    // [HID, K1] row-major
             const float* __restrict__ b1,
             int n_nodes)
{
    __shared__ float As[16][128];
    __shared__ float Bs[16][128];

    const int tid  = threadIdx.x;
    const int mblk = blockIdx.x * 128;
    const int nblk = blockIdx.y * 128;
    const int tx = tid & 15, ty = tid >> 4;

    unsigned long long acc[8][4];
#pragma unroll
    for (int i = 0; i < 8; i++)
#pragma unroll
        for (int j = 0; j < 4; j++) acc[i][j] = 0ull;

#pragma unroll 1
    for (int kt = 0; kt < 8; kt++) {
        const int k0 = kt * 16;
        if (kt) __syncthreads();
#pragma unroll
        for (int r = 0; r < 2; r++) {
            int id = tid + r * 256;
            int m  = id >> 2;
            int k4 = (id & 3) << 2;
            int row = mblk + m; if (row >= n_nodes) row = 0;
            float4 va = *(const float4*)(x + (size_t)row * IN_DIM + k0 + k4);
            As[k4 + 0][m] = va.x; As[k4 + 1][m] = va.y;
            As[k4 + 2][m] = va.z; As[k4 + 3][m] = va.w;
            float4 vb = *(const float4*)(W1 + (size_t)(nblk + m) * K1 + k0 + k4);
            Bs[k4 + 0][m] = vb.x; Bs[k4 + 1][m] = vb.y;
            Bs[k4 + 2][m] = vb.z; Bs[k4 + 3][m] = vb.w;
        }
        __syncthreads();
#pragma unroll
        for (int k = 0; k < 16; k++) {
            unsigned long long ap[8], bp[4];
            const float* arow = &As[k][ty * 8];
#pragma unroll
            for (int i = 0; i < 8; i++) ap[i] = pack2(arow[i]);
            bp[0] = *(const unsigned long long*)&Bs[k][tx * 4];
            bp[1] = *(const unsigned long long*)&Bs[k][tx * 4 + 2];
            bp[2] = *(const unsigned long long*)&Bs[k][64 + tx * 4];
            bp[3] = *(const unsigned long long*)&Bs[k][64 + tx * 4 + 2];
#pragma unroll
            for (int i = 0; i < 8; i++)
#pragma unroll
                for (int j = 0; j < 4; j++) fma2(acc[i][j], ap[i], bp[j]);
        }
    }

#pragma unroll
    for (int i = 0; i < 8; i++) {
        int m = mblk + ty * 8 + i;
        if (m >= n_nodes) continue;
        float* row = g_xh + (size_t)m * HID + nblk;
#pragma unroll
        for (int j = 0; j < 4; j++) {
            int n = (j < 2) ? (tx * 4 + 2 * j) : (64 + tx * 4 + 2 * (j - 2));
            float lo, hi;
            unpack2(acc[i][j], lo, hi);
            row[n]     = lo + b1[nblk + n];
            row[n + 1] = hi + b1[nblk + n + 1];
        }
    }
}

// =============================================================================
// Kernel B (fused): per 128-edge tile
//   phase1: T = ea @ W1e^T  (K=64);  h = relu(T + xh[src])  -> SMEM Hs[k][m]
//   phase2: msg = h @ W2^T  (K=256, A read directly from Hs); +b2; atomic scatter
// SMEM: Hs 256x129 f32 | Ea 64x128 | Bs 16x128 | src/dst/b2
// =============================================================================
#define HS_PITCH 129
#define SMEM_F  (256 * HS_PITCH + 64 * 128 + 16 * 128)
#define SMEM_DYN ((SMEM_F + 128 + 128 + 128) * 4)

__global__ __launch_bounds__(256, 1)
void gine_fused(const float* __restrict__ ea,
                const float* __restrict__ W1,   // [HID, K1]
                const float* __restrict__ W2,   // [OUT, HID]
                const float* __restrict__ b2v,
                float* __restrict__ out)
{
    extern __shared__ float sm[];
    float* Hs   = sm;                          // [256][129]
    float* Ea   = Hs + 256 * HS_PITCH;         // [64][128]
    float* Bs   = Ea + 64 * 128;               // [16][128]
    int*   s_src = (int*)(Bs + 16 * 128);      // [128]
    int*   s_dst = s_src + 128;                // [128]
    float* s_b2  = (float*)(s_dst + 128);      // [128]

    const int tid  = threadIdx.x;
    const int eblk = blockIdx.x * 128;
    const int tx = tid & 15, ty = tid >> 4;

    if (tid < 128) {
        s_src[tid] = g_src[eblk + tid];
        s_dst[tid] = g_dst[eblk + tid];
        s_b2[tid]  = b2v[tid];
    }

    // ---- stage Ea[k][m] (transpose of ea tile), 2048 float4 / 256 thr ----
#pragma unroll
    for (int r = 0; r < 8; r++) {
        int id = tid + r * 256;
        int m  = id & 127;
        int kq = id >> 7;                       // 0..15 -> k group of 4
        float4 v = *(const float4*)(ea + (size_t)(eblk + m) * EDGE_DIM + kq * 4);
        Ea[(kq * 4 + 0) * 128 + m] = v.x;
        Ea[(kq * 4 + 1) * 128 + m] = v.y;
        Ea[(kq * 4 + 2) * 128 + m] = v.z;
        Ea[(kq * 4 + 3) * 128 + m] = v.w;
    }
    __syncthreads();

    const int ldn = tid >> 2;        // 0..63 per 256 thr x2 iters -> n 0..127
    const int ldk = tid & 3;         // k-quad

    // ================= phase 1: two 128-wide HID passes, K=64 ================
#pragma unroll 1
    for (int p = 0; p < 2; p++) {
        unsigned long long acc[8][4];
#pragma unroll
        for (int i = 0; i < 8; i++)
#pragma unroll
            for (int j = 0; j < 4; j++) acc[i][j] = 0ull;

        // prefetch chunk 0 of this pass
        float4 pv0 = *(const float4*)(W1 + (size_t)(p * 128 + ldn)      * K1 + IN_DIM + ldk * 4);
        float4 pv1 = *(const float4*)(W1 + (size_t)(p * 128 + 64 + ldn) * K1 + IN_DIM + ldk * 4);

#pragma unroll 1
        for (int c = 0; c < 4; c++) {
            __syncthreads();                    // Bs readers of prev chunk done
            Bs[(ldk * 4 + 0) * 128 + ldn] = pv0.x;
            Bs[(ldk * 4 + 1) * 128 + ldn] = pv0.y;
            Bs[(ldk * 4 + 2) * 128 + ldn] = pv0.z;
            Bs[(ldk * 4 + 3) * 128 + ldn] = pv0.w;
            Bs[(ldk * 4 + 0) * 128 + 64 + ldn] = pv1.x;
            Bs[(ldk * 4 + 1) * 128 + 64 + ldn] = pv1.y;
            Bs[(ldk * 4 + 2) * 128 + 64 + ldn] = pv1.z;
            Bs[(ldk * 4 + 3) * 128 + 64 + ldn] = pv1.w;
            __syncthreads();
            if (c < 3) {                        // prefetch next chunk (overlaps FMAs)
                pv0 = *(const float4*)(W1 + (size_t)(p * 128 + ldn)      * K1 + IN_DIM + (c + 1) * 16 + ldk * 4);
                pv1 = *(const float4*)(W1 + (size_t)(p * 128 + 64 + ldn) * K1 + IN_DIM + (c + 1) * 16 + ldk * 4);
            }
#pragma unroll
            for (int k = 0; k < 16; k++) {
                unsigned long long ap[8], bp[4];
                const float* arow = &Ea[(c * 16 + k) * 128 + ty * 8];
#pragma unroll
                for (int i = 0; i < 8; i++) ap[i] = pack2(arow[i]);
                const float* brow = &Bs[k * 128];
                bp[0] = *(const unsigned long long*)&brow[tx * 4];
                bp[1] = *(const unsigned long long*)&brow[tx * 4 + 2];
                bp[2] = *(const unsigned long long*)&brow[64 + tx * 4];
                bp[3] = *(const unsigned long long*)&brow[64 + tx * 4 + 2];
#pragma unroll
                for (int i = 0; i < 8; i++)
#pragma unroll
                    for (int j = 0; j < 4; j++) fma2(acc[i][j], ap[i], bp[j]);
            }
        }

        // ---- epilogue pass p: h = relu(acc + xh[src])  -> Hs[k][m] ----
#pragma unroll
        for (int i = 0; i < 8; i++) {
            const int m = ty * 8 + i;
            const float* xr = g_xh + (size_t)s_src[m] * HID + p * 128;
#pragma unroll
            for (int j = 0; j < 4; j++) {
                int n = (j < 2) ? (tx * 4 + 2 * j) : (64 + tx * 4 + 2 * (j - 2));
                float lo, hi;
                unpack2(acc[i][j], lo, hi);
                float2 xv = *(const float2*)(xr + n);
                lo = fmaxf(lo + xv.x, 0.0f);
                hi = fmaxf(hi + xv.y, 0.0f);
                Hs[(p * 128 + n)     * HS_PITCH + m] = lo;
                Hs[(p * 128 + n + 1) * HS_PITCH + m] = hi;
            }
        }
    }

    // ================= phase 2: msg = h @ W2^T, K=256 ========================
    unsigned long long acc[8][4];
#pragma unroll
    for (int i = 0; i < 8; i++)
#pragma unroll
        for (int j = 0; j < 4; j++) acc[i][j] = 0ull;

    float4 pv0 = *(const float4*)(W2 + (size_t)ldn        * HID + ldk * 4);
    float4 pv1 = *(const float4*)(W2 + (size_t)(64 + ldn) * HID + ldk * 4);

#pragma unroll 1
    for (int c = 0; c < 16; c++) {
        __syncthreads();                        // also orders Hs writes before first reads
        Bs[(ldk * 4 + 0) * 128 + ldn] = pv0.x;
        Bs[(ldk * 4 + 1) * 128 + ldn] = pv0.y;
        Bs[(ldk * 4 + 2) * 128 + ldn] = pv0.z;
        Bs[(ldk * 4 + 3) * 128 + ldn] = pv0.w;
        Bs[(ldk * 4 + 0) * 128 + 64 + ldn] = pv1.x;
        Bs[(ldk * 4 + 1) * 128 + 64 + ldn] = pv1.y;
        Bs[(ldk * 4 + 2) * 128 + 64 + ldn] = pv1.z;
        Bs[(ldk * 4 + 3) * 128 + 64 + ldn] = pv1.w;
        __syncthreads();
        if (c < 15) {
            pv0 = *(const float4*)(W2 + (size_t)ldn        * HID + (c + 1) * 16 + ldk * 4);
            pv1 = *(const float4*)(W2 + (size_t)(64 + ldn) * HID + (c + 1) * 16 + ldk * 4);
        }
#pragma unroll
        for (int k = 0; k < 16; k++) {
            unsigned long long ap[8], bp[4];
            const float* arow = &Hs[(c * 16 + k) * HS_PITCH + ty * 8];
#pragma unroll
            for (int i = 0; i < 8; i++) ap[i] = pack2(arow[i]);
            const float* brow = &Bs[k * 128];
            bp[0] = *(const unsigned long long*)&brow[tx * 4];
            bp[1] = *(const unsigned long long*)&brow[tx * 4 + 2];
            bp[2] = *(const unsigned long long*)&brow[64 + tx * 4];
            bp[3] = *(const unsigned long long*)&brow[64 + tx * 4 + 2];
#pragma unroll
            for (int i = 0; i < 8; i++)
#pragma unroll
                for (int j = 0; j < 4; j++) fma2(acc[i][j], ap[i], bp[j]);
        }
    }

    // ---- epilogue: + b2, scatter-add ----
#pragma unroll
    for (int i = 0; i < 8; i++) {
        float* orow = out + (size_t)s_dst[ty * 8 + i] * OUT_DIM;
#pragma unroll
        for (int j = 0; j < 4; j++) {
            int n = (j < 2) ? (tx * 4 + 2 * j) : (64 + tx * 4 + 2 * (j - 2));
            float lo, hi;
            unpack2(acc[i][j], lo, hi);
            atomicAdd(orow + n,     lo + s_b2[n]);
            atomicAdd(orow + n + 1, hi + s_b2[n + 1]);
        }
    }
}

// =============================================================================
extern "C" void kernel_launch(void* const* d_in, const int* in_sizes, int n_in,
                              void* d_out, int out_size)
{
    const float* x  = (const float*)d_in[0];
    const void*  ei = d_in[1];
    const float* ea = (const float*)d_in[2];
    const float* W1 = (const float*)d_in[3];
    const float* b1 = (const float*)d_in[4];
    const float* W2 = (const float*)d_in[5];
    const float* b2 = (const float*)d_in[6];
    float*       out = (float*)d_out;

    const int E       = in_sizes[2] / EDGE_DIM;   // 640000
    const int n_nodes = in_sizes[0] / IN_DIM;     // 10000

    int zblk = (out_size + 255) / 256;
    if (zblk > 2960) zblk = 2960;
    zero_out_kernel<<<zblk, 256>>>(out, out_size);

    decode_edges<<<592, 256>>>(ei, E, n_nodes);

    dim3 gx((n_nodes + 127) / 128, HID / 128);
    xh_gemm<<<gx, 256>>>(x, W1, b1, n_nodes);

    cudaFuncSetAttribute(gine_fused, cudaFuncAttributeMaxDynamicSharedMemorySize, SMEM_DYN);
    gine_fused<<<E / 128, 256, SMEM_DYN>>>(ea, W1, W2, b2, out);
}

// round 15
// speedup vs baseline: 3.1668x; 2.0309x over previous
#include <cuda_runtime.h>
#include <cuda_bf16.h>
#include <cstdint>

#define IN_DIM   128
#define EDGE_DIM 64
#define K1       192   // IN_DIM + EDGE_DIM
#define HID      256
#define OUT_DIM  128
#define N_NODES_MAX 10000
#define N_EDGES_MAX 640000

// ---------------- device scratch (runtime allocation forbidden) --------------
__device__ int   g_src[N_EDGES_MAX];
__device__ int   g_dst[N_EDGES_MAX];
__device__ float g_xh[(size_t)N_NODES_MAX * HID];   // x @ W1x^T + b1 (exact fp32)
// Pre-split bf16 weight images, laid out exactly as the SMEM tiles (pitched):
// W1e: pass p in {0,1}: [128 n][pitch 72 k] hi (18432 B) then lo (18432 B)
__device__ char  g_W1img[2 * 36864];
// W2: chunk c in {0,1}: [128 n][pitch 136 k] hi (34816 B) then lo (34816 B)
__device__ char  g_W2img[2 * 69632];

// ---------------- packed f32x2 helpers (for the small xh GEMM) ---------------
__device__ __forceinline__ unsigned long long pack2(float x) {
    unsigned long long r;
    asm("mov.b64 %0, {%1, %1};" : "=l"(r) : "f"(x));
    return r;
}
__device__ __forceinline__ void fma2(unsigned long long& c,
                                     unsigned long long a,
                                     unsigned long long b) {
    asm("fma.rn.f32x2 %0, %1, %2, %0;" : "+l"(c) : "l"(a), "l"(b));
}
__device__ __forceinline__ void unpack2(unsigned long long c, float& lo, float& hi) {
    asm("mov.b64 {%0, %1}, %2;" : "=f"(lo), "=f"(hi) : "l"(c));
}

// ---------------- misc PTX ---------------------------------------------------
__device__ __forceinline__ uint32_t smem_u32(const void* p) {
    uint32_t a;
    asm("{ .reg .u64 t; cvta.to.shared.u64 t, %1; cvt.u32.u64 %0, t; }" : "=r"(a) : "l"(p));
    return a;
}
__device__ __forceinline__ void cp16(uint32_t dst, const void* src) {
    asm volatile("cp.async.cg.shared.global [%0], [%1], 16;" :: "r"(dst), "l"(src) : "memory");
}
#define CP_COMMIT() asm volatile("cp.async.commit_group;" ::: "memory")
#define CP_WAIT(N)  asm volatile("cp.async.wait_group %0;" :: "n"(N) : "memory")

__device__ __forceinline__ void mma16816(float* c, const uint32_t* a, const uint32_t* b) {
    asm volatile(
        "mma.sync.aligned.m16n8k16.row.col.f32.bf16.bf16.f32 "
        "{%0,%1,%2,%3}, {%4,%5,%6,%7}, {%8,%9}, {%0,%1,%2,%3};"
        : "+f"(c[0]), "+f"(c[1]), "+f"(c[2]), "+f"(c[3])
        : "r"(a[0]), "r"(a[1]), "r"(a[2]), "r"(a[3]), "r"(b[0]), "r"(b[1]));
}

// ---------------- prep kernels ----------------------------------------------
__global__ void zero_out_kernel(float* __restrict__ out, int n) {
    for (int i = blockIdx.x * blockDim.x + threadIdx.x; i < n;
         i += gridDim.x * blockDim.x)
        out[i] = 0.0f;
}

__global__ void decode_edges(const void* __restrict__ ei_raw, int E, int n_nodes) {
    const long long* e64 = (const long long*)ei_raw;
    const int*       e32 = (const int*)ei_raw;
    bool is64 = true;
#pragma unroll 1
    for (int i = 0; i < 64; i++) {
        long long v = e64[i];
        if (v < 0 || v >= (long long)n_nodes) { is64 = false; break; }
    }
    for (int e = blockIdx.x * blockDim.x + threadIdx.x; e < E;
         e += gridDim.x * blockDim.x) {
        if (is64) { g_src[e] = (int)e64[e]; g_dst[e] = (int)e64[(long)E + e]; }
        else      { g_src[e] = e32[e];      g_dst[e] = e32[E + e]; }
    }
}

__global__ void split_weights(const float* __restrict__ W1, const float* __restrict__ W2) {
    int i = blockIdx.x * blockDim.x + threadIdx.x;
    if (i < HID * EDGE_DIM) {                 // W1e: rows 0..255, k 0..63
        int r = i / EDGE_DIM, k = i % EDGE_DIM;
        float w = W1[(size_t)r * K1 + IN_DIM + k];
        __nv_bfloat16 hi = __float2bfloat16(w);
        __nv_bfloat16 lo = __float2bfloat16(w - __bfloat162float(hi));
        int p = r >> 7, n = r & 127;
        char* base = g_W1img + p * 36864;
        *(unsigned short*)(base + n * 144 + k * 2)         = __bfloat16_as_ushort(hi);
        *(unsigned short*)(base + 18432 + n * 144 + k * 2) = __bfloat16_as_ushort(lo);
    }
    if (i < OUT_DIM * HID) {                  // W2: rows 0..127, k 0..255
        int r = i / HID, k = i % HID;
        float w = W2[i];
        __nv_bfloat16 hi = __float2bfloat16(w);
        __nv_bfloat16 lo = __float2bfloat16(w - __bfloat162float(hi));
        int c = k >> 7, kk = k & 127;
        char* base = g_W2img + c * 69632;
        *(unsigned short*)(base + r * 272 + kk * 2)         = __bfloat16_as_ushort(hi);
        *(unsigned short*)(base + 34816 + r * 272 + kk * 2) = __bfloat16_as_ushort(lo);
    }
}

// =============================================================================
// Kernel A: g_xh[n,:] = x[n,:] @ W1x^T + b1 (fp32-exact, FFMA2)
// =============================================================================
__global__ __launch_bounds__(256, 2)
void xh_gemm(const float* __restrict__ x,
             const float* __restrict__ W1, const float* __restrict__ b1,
             int n_nodes)
{
    __shared__ float As[16][128];
    __shared__ float Bs[16][128];
    const int tid = threadIdx.x;
    const int mblk = blockIdx.x * 128, nblk = blockIdx.y * 128;
    const int tx = tid & 15, ty = tid >> 4;
    unsigned long long acc[8][4];
#pragma unroll
    for (int i = 0; i < 8; i++)
#pragma unroll
        for (int j = 0; j < 4; j++) acc[i][j] = 0ull;
#pragma unroll 1
    for (int kt = 0; kt < 8; kt++) {
        const int k0 = kt * 16;
        if (kt) __syncthreads();
#pragma unroll
        for (int r = 0; r < 2; r++) {
            int id = tid + r * 256;
            int m = id >> 2, k4 = (id & 3) << 2;
            int row = mblk + m; if (row >= n_nodes) row = 0;
            float4 va = *(const float4*)(x + (size_t)row * IN_DIM + k0 + k4);
            As[k4 + 0][m] = va.x; As[k4 + 1][m] = va.y;
            As[k4 + 2][m] = va.z; As[k4 + 3][m] = va.w;
            float4 vb = *(const float4*)(W1 + (size_t)(nblk + m) * K1 + k0 + k4);
            Bs[k4 + 0][m] = vb.x; Bs[k4 + 1][m] = vb.y;
            Bs[k4 + 2][m] = vb.z; Bs[k4 + 3][m] = vb.w;
        }
        __syncthreads();
#pragma unroll
        for (int k = 0; k < 16; k++) {
            unsigned long long ap[8], bp[4];
            const float* arow = &As[k][ty * 8];
#pragma unroll
            for (int i = 0; i < 8; i++) ap[i] = pack2(arow[i]);
            bp[0] = *(const unsigned long long*)&Bs[k][tx * 4];
            bp[1] = *(const unsigned long long*)&Bs[k][tx * 4 + 2];
            bp[2] = *(const unsigned long long*)&Bs[k][64 + tx * 4];
            bp[3] = *(const unsigned long long*)&Bs[k][64 + tx * 4 + 2];
#pragma unroll
            for (int i = 0; i < 8; i++)
#pragma unroll
                for (int j = 0; j < 4; j++) fma2(acc[i][j], ap[i], bp[j]);
        }
    }
#pragma unroll
    for (int i = 0; i < 8; i++) {
        int m = mblk + ty * 8 + i;
        if (m >= n_nodes) continue;
        float* row = g_xh + (size_t)m * HID + nblk;
#pragma unroll
        for (int j = 0; j < 4; j++) {
            int n = (j < 2) ? (tx * 4 + 2 * j) : (64 + tx * 4 + 2 * (j - 2));
            float lo, hi;
            unpack2(acc[i][j], lo, hi);
            row[n] = lo + b1[nblk + n];
            row[n + 1] = hi + b1[nblk + n + 1];
        }
    }
}

// =============================================================================
// Fused edge kernel: bf16 3-term HMMA.
// SMEM byte offsets (all tiles pitched for conflict-free frag loads):
#define EAH 0u            // ea hi  [128][72]b16 = 18432
#define EAL 18432u        // ea lo
#define HH  36864u        // h hi   [128][136]   = 34816
#define HL  71680u        // h lo
#define W1H 106496u       // W1e hi [128][72]
#define W1L 124928u       // W1e lo
#define W2H 143360u       // W2 hi  [128][136]
#define W2L 178176u       // W2 lo
#define SSRC 212992u      // int[128]
#define SDST 213504u
#define SB2  214016u      // float[128]
#define SMEM_DYN 214528u

// 3-term (hh + lh + hl) K-loop; PITCHB = tile row pitch in bytes.
template<int KSTEPS, int PITCHB>
__device__ __forceinline__ void gemm3(const char* aH, const char* aL,
                                      const char* bH, const char* bL,
                                      float acc[2][8][4],
                                      int g, int t, int wm, int wn)
{
#pragma unroll 1
    for (int kt = 0; kt < KSTEPS; kt++) {
        const int kb = kt * 32 + t * 4;            // (kt*16 + t*2) bf16 -> bytes
        uint32_t ah[2][4], al[2][4], bh[8][2], bl[8][2];
#pragma unroll
        for (int mt = 0; mt < 2; mt++) {
            const char* p = aH + (wm * 32 + mt * 16 + g) * PITCHB + kb;
            ah[mt][0] = *(const uint32_t*)p;
            ah[mt][1] = *(const uint32_t*)(p + 8 * PITCHB);
            ah[mt][2] = *(const uint32_t*)(p + 16);
            ah[mt][3] = *(const uint32_t*)(p + 8 * PITCHB + 16);
        }
#pragma unroll
        for (int nt = 0; nt < 8; nt++) {
            const char* p = bH + (wn * 64 + nt * 8 + g) * PITCHB + kb;
            bh[nt][0] = *(const uint32_t*)p;
            bh[nt][1] = *(const uint32_t*)(p + 16);
        }
#pragma unroll
        for (int mt = 0; mt < 2; mt++)
#pragma unroll
            for (int nt = 0; nt < 8; nt++) mma16816(acc[mt][nt], ah[mt], bh[nt]);
#pragma unroll
        for (int mt = 0; mt < 2; mt++) {
            const char* p = aL + (wm * 32 + mt * 16 + g) * PITCHB + kb;
            al[mt][0] = *(const uint32_t*)p;
            al[mt][1] = *(const uint32_t*)(p + 8 * PITCHB);
            al[mt][2] = *(const uint32_t*)(p + 16);
            al[mt][3] = *(const uint32_t*)(p + 8 * PITCHB + 16);
        }
#pragma unroll
        for (int mt = 0; mt < 2; mt++)
#pragma unroll
            for (int nt = 0; nt < 8; nt++) mma16816(acc[mt][nt], al[mt], bh[nt]);
#pragma unroll
        for (int nt = 0; nt < 8; nt++) {
            const char* p = bL + (wn * 64 + nt * 8 + g) * PITCHB + kb;
            bl[nt][0] = *(const uint32_t*)p;
            bl[nt][1] = *(const uint32_t*)(p + 16);
        }
#pragma unroll
        for (int mt = 0; mt < 2; mt++)
#pragma unroll
            for (int nt = 0; nt < 8; nt++) mma16816(acc[mt][nt], ah[mt], bl[nt]);
    }
}

// epilogue1: h = relu(acc + xh[src]) -> split bf16 into hbuf
__device__ __forceinline__ void epilogue_h(float acc[2][8][4], const int* s_src,
                                           char* hHp, char* hLp,
                                           int p, int g, int t, int wm, int wn)
{
#pragma unroll
    for (int mt = 0; mt < 2; mt++)
#pragma unroll
        for (int half = 0; half < 2; half++) {
            int r = wm * 32 + mt * 16 + g + half * 8;
            const float* xr = g_xh + (size_t)s_src[r] * HID + p * 128 + wn * 64;
#pragma unroll
            for (int nt = 0; nt < 8; nt++) {
                int c = nt * 8 + t * 2;
                float2 xv = *(const float2*)(xr + c);
                float v0 = fmaxf(acc[mt][nt][half * 2 + 0] + xv.x, 0.0f);
                float v1 = fmaxf(acc[mt][nt][half * 2 + 1] + xv.y, 0.0f);
                __nv_bfloat16 h0 = __float2bfloat16(v0), h1 = __float2bfloat16(v1);
                __nv_bfloat16 l0 = __float2bfloat16(v0 - __bfloat162float(h0));
                __nv_bfloat16 l1 = __float2bfloat16(v1 - __bfloat162float(h1));
                uint32_t hw = (uint32_t)__bfloat16_as_ushort(h0)
                            | ((uint32_t)__bfloat16_as_ushort(h1) << 16);
                uint32_t lw = (uint32_t)__bfloat16_as_ushort(l0)
                            | ((uint32_t)__bfloat16_as_ushort(l1) << 16);
                int col = wn * 64 + c;
                *(uint32_t*)(hHp + r * 272 + col * 2) = hw;
                *(uint32_t*)(hLp + r * 272 + col * 2) = lw;
            }
        }
}

__global__ __launch_bounds__(256)
void gine_fused(const float* __restrict__ ea,
                const float* __restrict__ b2v,
                float* __restrict__ out)
{
    extern __shared__ char sm[];
    const uint32_t sbase = smem_u32(sm);
    const int tid = threadIdx.x;
    const int eblk = blockIdx.x * 128;
    const int lane = tid & 31, wid = tid >> 5;
    const int g = lane >> 2, t = lane & 3;
    const int wm = wid & 3, wn = wid >> 2;

    // prefetch W1 pass0 + W2 chunk0 (cp.async, groups 0 and 1)
    for (int off = tid * 16; off < 36864; off += 4096) cp16(sbase + W1H + off, g_W1img + off);
    CP_COMMIT();
    for (int off = tid * 16; off < 69632; off += 4096) cp16(sbase + W2H + off, g_W2img + off);
    CP_COMMIT();

    // stage src/dst/b2
    if (tid < 128) {
        ((int*)(sm + SSRC))[tid] = g_src[eblk + tid];
        ((int*)(sm + SDST))[tid] = g_dst[eblk + tid];
        ((float*)(sm + SB2))[tid] = b2v[tid];
    }
    // stage ea -> bf16 hi/lo tiles
#pragma unroll
    for (int r = 0; r < 8; r++) {
        int id = tid + r * 256;
        int m = id >> 4, kq = id & 15;
        float4 v = *(const float4*)(ea + (size_t)(eblk + m) * EDGE_DIM + kq * 4);
        __nv_bfloat16 h0 = __float2bfloat16(v.x), h1 = __float2bfloat16(v.y);
        __nv_bfloat16 h2 = __float2bfloat16(v.z), h3 = __float2bfloat16(v.w);
        __nv_bfloat16 l0 = __float2bfloat16(v.x - __bfloat162float(h0));
        __nv_bfloat16 l1 = __float2bfloat16(v.y - __bfloat162float(h1));
        __nv_bfloat16 l2 = __float2bfloat16(v.z - __bfloat162float(h2));
        __nv_bfloat16 l3 = __float2bfloat16(v.w - __bfloat162float(h3));
        char* dh = sm + EAH + m * 144 + kq * 8;
        char* dl = sm + EAL + m * 144 + kq * 8;
        *(uint32_t*)dh       = (uint32_t)__bfloat16_as_ushort(h0) | ((uint32_t)__bfloat16_as_ushort(h1) << 16);
        *(uint32_t*)(dh + 4) = (uint32_t)__bfloat16_as_ushort(h2) | ((uint32_t)__bfloat16_as_ushort(h3) << 16);
        *(uint32_t*)dl       = (uint32_t)__bfloat16_as_ushort(l0) | ((uint32_t)__bfloat16_as_ushort(l1) << 16);
        *(uint32_t*)(dl + 4) = (uint32_t)__bfloat16_as_ushort(l2) | ((uint32_t)__bfloat16_as_ushort(l3) << 16);
    }

    const int* s_src = (const int*)(sm + SSRC);
    const int* s_dst = (const int*)(sm + SDST);
    const float* s_b2 = (const float*)(sm + SB2);

    float acc1[2][8][4], acc2[2][8][4];
#pragma unroll
    for (int i = 0; i < 2; i++)
#pragma unroll
        for (int j = 0; j < 8; j++)
#pragma unroll
            for (int k = 0; k < 4; k++) { acc1[i][j][k] = 0.f; acc2[i][j][k] = 0.f; }

    CP_WAIT(1);           // W1 pass0 landed (W2 chunk0 may be in flight)
    __syncthreads();

    // ---- GEMM1 pass 0 (hid 0..127), K=64 ----
    gemm3<4, 144>(sm + EAH, sm + EAL, sm + W1H, sm + W1L, acc1, g, t, wm, wn);
    __syncthreads();                                    // all done reading W1 buf
    for (int off = tid * 16; off < 36864; off += 4096)  // prefetch W1 pass1 (group2)
        cp16(sbase + W1H + off, g_W1img + 36864 + off);
    CP_COMMIT();
    epilogue_h(acc1, s_src, sm + HH, sm + HL, 0, g, t, wm, wn);
    CP_WAIT(1);           // W2 chunk0 landed (group2 pending)
    __syncthreads();      // hbuf coherent + W2 visible to all

    // ---- GEMM2 chunk 0 (k 0..127) ----
    gemm3<8, 272>(sm + HH, sm + HL, sm + W2H, sm + W2L, acc2, g, t, wm, wn);
    __syncthreads();                                    // done reading W2 buf + hbuf
    for (int off = tid * 16; off < 69632; off += 4096)  // prefetch W2 chunk1 (group3)
        cp16(sbase + W2H + off, g_W2img + 69632 + off);
    CP_COMMIT();
    CP_WAIT(1);           // W1 pass1 landed (group3 pending)
    __syncthreads();

    // ---- GEMM1 pass 1 (hid 128..255) ----
#pragma unroll
    for (int i = 0; i < 2; i++)
#pragma unroll
        for (int j = 0; j < 8; j++)
#pragma unroll
            for (int k = 0; k < 4; k++) acc1[i][j][k] = 0.f;
    gemm3<4, 144>(sm + EAH, sm + EAL, sm + W1H, sm + W1L, acc1, g, t, wm, wn);
    __syncthreads();
    epilogue_h(acc1, s_src, sm + HH, sm + HL, 1, g, t, wm, wn);
    CP_WAIT(0);           // W2 chunk1 landed
    __syncthreads();

    // ---- GEMM2 chunk 1 (k 128..255) ----
    gemm3<8, 272>(sm + HH, sm + HL, sm + W2H, sm + W2L, acc2, g, t, wm, wn);

    // ---- epilogue: + b2, atomic scatter ----
#pragma unroll
    for (int mt = 0; mt < 2; mt++)
#pragma unroll
        for (int half = 0; half < 2; half++) {
            int r = wm * 32 + mt * 16 + g + half * 8;
            float* orow = out + (size_t)s_dst[r] * OUT_DIM;
#pragma unroll
            for (int nt = 0; nt < 8; nt++) {
                int c = wn * 64 + nt * 8 + t * 2;
                atomicAdd(orow + c,     acc2[mt][nt][half * 2 + 0] + s_b2[c]);
                atomicAdd(orow + c + 1, acc2[mt][nt][half * 2 + 1] + s_b2[c + 1]);
            }
        }
}

// =============================================================================
extern "C" void kernel_launch(void* const* d_in, const int* in_sizes, int n_in,
                              void* d_out, int out_size)
{
    const float* x  = (const float*)d_in[0];
    const void*  ei = d_in[1];
    const float* ea = (const float*)d_in[2];
    const float* W1 = (const float*)d_in[3];
    const float* b1 = (const float*)d_in[4];
    const float* W2 = (const float*)d_in[5];
    const float* b2 = (const float*)d_in[6];
    float*       out = (float*)d_out;

    const int E       = in_sizes[2] / EDGE_DIM;   // 640000
    const int n_nodes = in_sizes[0] / IN_DIM;     // 10000

    int zblk = (out_size + 255) / 256;
    if (zblk > 2960) zblk = 2960;
    zero_out_kernel<<<zblk, 256>>>(out, out_size);

    decode_edges<<<592, 256>>>(ei, E, n_nodes);
    split_weights<<<(OUT_DIM * HID + 255) / 256, 256>>>(W1, W2);

    dim3 gx((n_nodes + 127) / 128, HID / 128);
    xh_gemm<<<gx, 256>>>(x, W1, b1, n_nodes);

    cudaFuncSetAttribute(gine_fused, cudaFuncAttributeMaxDynamicSharedMemorySize, SMEM_DYN);
    gine_fused<<<E / 128, 256, SMEM_DYN>>>(ea, b2, out);
}

// round 16
// speedup vs baseline: 3.7763x; 1.1925x over previous
#include <cuda_runtime.h>
#include <cuda_fp16.h>
#include <cstdint>

#define IN_DIM   128
#define EDGE_DIM 64
#define K1       192   // IN_DIM + EDGE_DIM
#define HID      256
#define OUT_DIM  128
#define N_NODES_MAX 10000
#define N_EDGES_MAX 640000

// ---------------- device scratch (runtime allocation forbidden) --------------
__device__ int   g_src[N_EDGES_MAX];
__device__ int   g_dst[N_EDGES_MAX];
__device__ float g_xh[(size_t)N_NODES_MAX * HID];   // x @ W1x^T + b1 (exact fp32)
// Pre-split fp16 weight images, laid out exactly as the SMEM tiles (pitched):
// W1e: pass p in {0,1}: [128 n][pitch 72 k] hi (18432 B) then lo (18432 B)
__device__ char  g_W1img[2 * 36864];
// W2: chunk c in {0,1}: [128 n][pitch 136 k] hi (34816 B) then lo (34816 B)
__device__ char  g_W2img[2 * 69632];

// ---------------- packed f32x2 helpers (for the small xh GEMM) ---------------
__device__ __forceinline__ unsigned long long pack2(float x) {
    unsigned long long r;
    asm("mov.b64 %0, {%1, %1};" : "=l"(r) : "f"(x));
    return r;
}
__device__ __forceinline__ void fma2(unsigned long long& c,
                                     unsigned long long a,
                                     unsigned long long b) {
    asm("fma.rn.f32x2 %0, %1, %2, %0;" : "+l"(c) : "l"(a), "l"(b));
}
__device__ __forceinline__ void unpack2(unsigned long long c, float& lo, float& hi) {
    asm("mov.b64 {%0, %1}, %2;" : "=f"(lo), "=f"(hi) : "l"(c));
}

// ---------------- misc PTX ---------------------------------------------------
__device__ __forceinline__ uint32_t smem_u32(const void* p) {
    uint32_t a;
    asm("{ .reg .u64 t; cvta.to.shared.u64 t, %1; cvt.u32.u64 %0, t; }" : "=r"(a) : "l"(p));
    return a;
}
__device__ __forceinline__ void cp16(uint32_t dst, const void* src) {
    asm volatile("cp.async.cg.shared.global [%0], [%1], 16;" :: "r"(dst), "l"(src) : "memory");
}
#define CP_COMMIT() asm volatile("cp.async.commit_group;" ::: "memory")
#define CP_WAIT(N)  asm volatile("cp.async.wait_group %0;" :: "n"(N) : "memory")

__device__ __forceinline__ void mma16816(float* c, const uint32_t* a, const uint32_t* b) {
    asm volatile(
        "mma.sync.aligned.m16n8k16.row.col.f32.f16.f16.f32 "
        "{%0,%1,%2,%3}, {%4,%5,%6,%7}, {%8,%9}, {%0,%1,%2,%3};"
        : "+f"(c[0]), "+f"(c[1]), "+f"(c[2]), "+f"(c[3])
        : "r"(a[0]), "r"(a[1]), "r"(a[2]), "r"(a[3]), "r"(b[0]), "r"(b[1]));
}

// ---------------- prep kernels ----------------------------------------------
__global__ void zero_out_kernel(float* __restrict__ out, int n) {
    for (int i = blockIdx.x * blockDim.x + threadIdx.x; i < n;
         i += gridDim.x * blockDim.x)
        out[i] = 0.0f;
}

__global__ void decode_edges(const void* __restrict__ ei_raw, int E, int n_nodes) {
    const long long* e64 = (const long long*)ei_raw;
    const int*       e32 = (const int*)ei_raw;
    bool is64 = true;
#pragma unroll 1
    for (int i = 0; i < 64; i++) {
        long long v = e64[i];
        if (v < 0 || v >= (long long)n_nodes) { is64 = false; break; }
    }
    for (int e = blockIdx.x * blockDim.x + threadIdx.x; e < E;
         e += gridDim.x * blockDim.x) {
        if (is64) { g_src[e] = (int)e64[e]; g_dst[e] = (int)e64[(long)E + e]; }
        else      { g_src[e] = e32[e];      g_dst[e] = e32[E + e]; }
    }
}

__global__ void split_weights(const float* __restrict__ W1, const float* __restrict__ W2) {
    int i = blockIdx.x * blockDim.x + threadIdx.x;
    if (i < HID * EDGE_DIM) {                 // W1e: rows 0..255, k 0..63
        int r = i / EDGE_DIM, k = i % EDGE_DIM;
        float w = W1[(size_t)r * K1 + IN_DIM + k];
        __half hi = __float2half_rn(w);
        __half lo = __float2half_rn(w - __half2float(hi));
        int p = r >> 7, n = r & 127;
        char* base = g_W1img + p * 36864;
        *(unsigned short*)(base + n * 144 + k * 2)         = __half_as_ushort(hi);
        *(unsigned short*)(base + 18432 + n * 144 + k * 2) = __half_as_ushort(lo);
    }
    if (i < OUT_DIM * HID) {                  // W2: rows 0..127, k 0..255
        int r = i / HID, k = i % HID;
        float w = W2[i];
        __half hi = __float2half_rn(w);
        __half lo = __float2half_rn(w - __half2float(hi));
        int c = k >> 7, kk = k & 127;
        char* base = g_W2img + c * 69632;
        *(unsigned short*)(base + r * 272 + kk * 2)         = __half_as_ushort(hi);
        *(unsigned short*)(base + 34816 + r * 272 + kk * 2) = __half_as_ushort(lo);
    }
}

// =============================================================================
// Kernel A: g_xh[n,:] = x[n,:] @ W1x^T + b1 (fp32-exact, FFMA2)
// =============================================================================
__global__ __launch_bounds__(256, 2)
void xh_gemm(const float* __restrict__ x,
             const float* __restrict__ W1, const float* __restrict__ b1,
             int n_nodes)
{
    __shared__ float As[16][128];
    __shared__ float Bs[16][128];
    const int tid = threadIdx.x;
    const int mblk = blockIdx.x * 128, nblk = blockIdx.y * 128;
    const int tx = tid & 15, ty = tid >> 4;
    unsigned long long acc[8][4];
#pragma unroll
    for (int i = 0; i < 8; i++)
#pragma unroll
        for (int j = 0; j < 4; j++) acc[i][j] = 0ull;
#pragma unroll 1
    for (int kt = 0; kt < 8; kt++) {
        const int k0 = kt * 16;
        if (kt) __syncthreads();
#pragma unroll
        for (int r = 0; r < 2; r++) {
            int id = tid + r * 256;
            int m = id >> 2, k4 = (id & 3) << 2;
            int row = mblk + m; if (row >= n_nodes) row = 0;
            float4 va = *(const float4*)(x + (size_t)row * IN_DIM + k0 + k4);
            As[k4 + 0][m] = va.x; As[k4 + 1][m] = va.y;
            As[k4 + 2][m] = va.z; As[k4 + 3][m] = va.w;
            float4 vb = *(const float4*)(W1 + (size_t)(nblk + m) * K1 + k0 + k4);
            Bs[k4 + 0][m] = vb.x; Bs[k4 + 1][m] = vb.y;
            Bs[k4 + 2][m] = vb.z; Bs[k4 + 3][m] = vb.w;
        }
        __syncthreads();
#pragma unroll
        for (int k = 0; k < 16; k++) {
            unsigned long long ap[8], bp[4];
            const float* arow = &As[k][ty * 8];
#pragma unroll
            for (int i = 0; i < 8; i++) ap[i] = pack2(arow[i]);
            bp[0] = *(const unsigned long long*)&Bs[k][tx * 4];
            bp[1] = *(const unsigned long long*)&Bs[k][tx * 4 + 2];
            bp[2] = *(const unsigned long long*)&Bs[k][64 + tx * 4];
            bp[3] = *(const unsigned long long*)&Bs[k][64 + tx * 4 + 2];
#pragma unroll
            for (int i = 0; i < 8; i++)
#pragma unroll
                for (int j = 0; j < 4; j++) fma2(acc[i][j], ap[i], bp[j]);
        }
    }
#pragma unroll
    for (int i = 0; i < 8; i++) {
        int m = mblk + ty * 8 + i;
        if (m >= n_nodes) continue;
        float* row = g_xh + (size_t)m * HID + nblk;
#pragma unroll
        for (int j = 0; j < 4; j++) {
            int n = (j < 2) ? (tx * 4 + 2 * j) : (64 + tx * 4 + 2 * (j - 2));
            float lo, hi;
            unpack2(acc[i][j], lo, hi);
            row[n] = lo + b1[nblk + n];
            row[n + 1] = hi + b1[nblk + n + 1];
        }
    }
}

// =============================================================================
// Fused edge kernel: fp16 HMMA. GEMM1 3-term (exact), GEMM2 2-term (W2-corrected).
// SMEM byte offsets:
#define EAH 0u            // ea hi  [128][72]f16 = 18432
#define EAL 18432u        // ea lo
#define HH  36864u        // h (single fp16) [128][136] pitch 272 = 34816 (one 128-k chunk)
#define W1H 71680u        // W1e hi [128][72]
#define W1L 90112u        // W1e lo
#define W2H 108544u       // W2 hi  [128][136]
#define W2L 143360u       // W2 lo
#define SSRC 178176u      // int[128]
#define SDST 178688u
#define SB2  179200u      // float[128]
#define SMEM_DYN 179712u

// 3-term (hh + lh + hl) K-loop; PITCHB = tile row pitch in bytes.
template<int KSTEPS, int PITCHB>
__device__ __forceinline__ void gemm3(const char* aH, const char* aL,
                                      const char* bH, const char* bL,
                                      float acc[2][8][4],
                                      int g, int t, int wm, int wn)
{
#pragma unroll 1
    for (int kt = 0; kt < KSTEPS; kt++) {
        const int kb = kt * 32 + t * 4;            // (kt*16 + t*2) f16 -> bytes
        uint32_t ah[2][4], al[2][4], bh[8][2], bl[8][2];
#pragma unroll
        for (int mt = 0; mt < 2; mt++) {
            const char* p = aH + (wm * 32 + mt * 16 + g) * PITCHB + kb;
            ah[mt][0] = *(const uint32_t*)p;
            ah[mt][1] = *(const uint32_t*)(p + 8 * PITCHB);
            ah[mt][2] = *(const uint32_t*)(p + 16);
            ah[mt][3] = *(const uint32_t*)(p + 8 * PITCHB + 16);
        }
#pragma unroll
        for (int nt = 0; nt < 8; nt++) {
            const char* p = bH + (wn * 64 + nt * 8 + g) * PITCHB + kb;
            bh[nt][0] = *(const uint32_t*)p;
            bh[nt][1] = *(const uint32_t*)(p + 16);
        }
#pragma unroll
        for (int mt = 0; mt < 2; mt++)
#pragma unroll
            for (int nt = 0; nt < 8; nt++) mma16816(acc[mt][nt], ah[mt], bh[nt]);
#pragma unroll
        for (int mt = 0; mt < 2; mt++) {
            const char* p = aL + (wm * 32 + mt * 16 + g) * PITCHB + kb;
            al[mt][0] = *(const uint32_t*)p;
            al[mt][1] = *(const uint32_t*)(p + 8 * PITCHB);
            al[mt][2] = *(const uint32_t*)(p + 16);
            al[mt][3] = *(const uint32_t*)(p + 8 * PITCHB + 16);
        }
#pragma unroll
        for (int mt = 0; mt < 2; mt++)
#pragma unroll
            for (int nt = 0; nt < 8; nt++) mma16816(acc[mt][nt], al[mt], bh[nt]);
#pragma unroll
        for (int nt = 0; nt < 8; nt++) {
            const char* p = bL + (wn * 64 + nt * 8 + g) * PITCHB + kb;
            bl[nt][0] = *(const uint32_t*)p;
            bl[nt][1] = *(const uint32_t*)(p + 16);
        }
#pragma unroll
        for (int mt = 0; mt < 2; mt++)
#pragma unroll
            for (int nt = 0; nt < 8; nt++) mma16816(acc[mt][nt], ah[mt], bl[nt]);
    }
}

// 2-term K-loop for GEMM2: acc += A*(Bh + Bl), A single fp16.
template<int KSTEPS, int PITCHB>
__device__ __forceinline__ void gemm2t(const char* aH,
                                       const char* bH, const char* bL,
                                       float acc[2][8][4],
                                       int g, int t, int wm, int wn)
{
#pragma unroll 1
    for (int kt = 0; kt < KSTEPS; kt++) {
        const int kb = kt * 32 + t * 4;
        uint32_t ah[2][4], bh[8][2], bl[8][2];
#pragma unroll
        for (int mt = 0; mt < 2; mt++) {
            const char* p = aH + (wm * 32 + mt * 16 + g) * PITCHB + kb;
            ah[mt][0] = *(const uint32_t*)p;
            ah[mt][1] = *(const uint32_t*)(p + 8 * PITCHB);
            ah[mt][2] = *(const uint32_t*)(p + 16);
            ah[mt][3] = *(const uint32_t*)(p + 8 * PITCHB + 16);
        }
#pragma unroll
        for (int nt = 0; nt < 8; nt++) {
            const char* p = bH + (wn * 64 + nt * 8 + g) * PITCHB + kb;
            bh[nt][0] = *(const uint32_t*)p;
            bh[nt][1] = *(const uint32_t*)(p + 16);
        }
#pragma unroll
        for (int mt = 0; mt < 2; mt++)
#pragma unroll
            for (int nt = 0; nt < 8; nt++) mma16816(acc[mt][nt], ah[mt], bh[nt]);
#pragma unroll
        for (int nt = 0; nt < 8; nt++) {
            const char* p = bL + (wn * 64 + nt * 8 + g) * PITCHB + kb;
            bl[nt][0] = *(const uint32_t*)p;
            bl[nt][1] = *(const uint32_t*)(p + 16);
        }
#pragma unroll
        for (int mt = 0; mt < 2; mt++)
#pragma unroll
            for (int nt = 0; nt < 8; nt++) mma16816(acc[mt][nt], ah[mt], bl[nt]);
    }
}

// epilogue1: h = relu(acc + xh[src]) -> single fp16 into h buffer
__device__ __forceinline__ void epilogue_h(float acc[2][8][4], const int* s_src,
                                           char* hHp,
                                           int p, int g, int t, int wm, int wn)
{
#pragma unroll
    for (int mt = 0; mt < 2; mt++)
#pragma unroll
        for (int half = 0; half < 2; half++) {
            int r = wm * 32 + mt * 16 + g + half * 8;
            const float* xr = g_xh + (size_t)s_src[r] * HID + p * 128 + wn * 64;
#pragma unroll
            for (int nt = 0; nt < 8; nt++) {
                int c = nt * 8 + t * 2;
                float2 xv = *(const float2*)(xr + c);
                float v0 = fmaxf(acc[mt][nt][half * 2 + 0] + xv.x, 0.0f);
                float v1 = fmaxf(acc[mt][nt][half * 2 + 1] + xv.y, 0.0f);
                __half h0 = __float2half_rn(v0), h1 = __float2half_rn(v1);
                uint32_t hw = (uint32_t)__half_as_ushort(h0)
                            | ((uint32_t)__half_as_ushort(h1) << 16);
                int col = wn * 64 + c;
                *(uint32_t*)(hHp + r * 272 + col * 2) = hw;
            }
        }
}

__global__ __launch_bounds__(256)
void gine_fused(const float* __restrict__ ea,
                const float* __restrict__ b2v,
                float* __restrict__ out)
{
    extern __shared__ char sm[];
    const uint32_t sbase = smem_u32(sm);
    const int tid = threadIdx.x;
    const int eblk = blockIdx.x * 128;
    const int lane = tid & 31, wid = tid >> 5;
    const int g = lane >> 2, t = lane & 3;
    const int wm = wid & 3, wn = wid >> 2;

    // prefetch W1 pass0 + W2 chunk0 (cp.async, groups 0 and 1)
    for (int off = tid * 16; off < 36864; off += 4096) cp16(sbase + W1H + off, g_W1img + off);
    CP_COMMIT();
    for (int off = tid * 16; off < 69632; off += 4096) cp16(sbase + W2H + off, g_W2img + off);
    CP_COMMIT();

    // stage src/dst/b2
    if (tid < 128) {
        ((int*)(sm + SSRC))[tid] = g_src[eblk + tid];
        ((int*)(sm + SDST))[tid] = g_dst[eblk + tid];
        ((float*)(sm + SB2))[tid] = b2v[tid];
    }
    // stage ea -> fp16 hi/lo tiles
#pragma unroll
    for (int r = 0; r < 8; r++) {
        int id = tid + r * 256;
        int m = id >> 4, kq = id & 15;
        float4 v = *(const float4*)(ea + (size_t)(eblk + m) * EDGE_DIM + kq * 4);
        __half h0 = __float2half_rn(v.x), h1 = __float2half_rn(v.y);
        __half h2 = __float2half_rn(v.z), h3 = __float2half_rn(v.w);
        __half l0 = __float2half_rn(v.x - __half2float(h0));
        __half l1 = __float2half_rn(v.y - __half2float(h1));
        __half l2 = __float2half_rn(v.z - __half2float(h2));
        __half l3 = __float2half_rn(v.w - __half2float(h3));
        char* dh = sm + EAH + m * 144 + kq * 8;
        char* dl = sm + EAL + m * 144 + kq * 8;
        *(uint32_t*)dh       = (uint32_t)__half_as_ushort(h0) | ((uint32_t)__half_as_ushort(h1) << 16);
        *(uint32_t*)(dh + 4) = (uint32_t)__half_as_ushort(h2) | ((uint32_t)__half_as_ushort(h3) << 16);
        *(uint32_t*)dl       = (uint32_t)__half_as_ushort(l0) | ((uint32_t)__half_as_ushort(l1) << 16);
        *(uint32_t*)(dl + 4) = (uint32_t)__half_as_ushort(l2) | ((uint32_t)__half_as_ushort(l3) << 16);
    }

    const int* s_src = (const int*)(sm + SSRC);
    const int* s_dst = (const int*)(sm + SDST);
    const float* s_b2 = (const float*)(sm + SB2);

    float acc1[2][8][4], acc2[2][8][4];
#pragma unroll
    for (int i = 0; i < 2; i++)
#pragma unroll
        for (int j = 0; j < 8; j++)
#pragma unroll
            for (int k = 0; k < 4; k++) { acc1[i][j][k] = 0.f; acc2[i][j][k] = 0.f; }

    CP_WAIT(1);           // W1 pass0 landed (W2 chunk0 may be in flight)
    __syncthreads();

    // ---- GEMM1 pass 0 (hid 0..127), K=64, 3-term ----
    gemm3<4, 144>(sm + EAH, sm + EAL, sm + W1H, sm + W1L, acc1, g, t, wm, wn);
    __syncthreads();                                    // all done reading W1 buf
    for (int off = tid * 16; off < 36864; off += 4096)  // prefetch W1 pass1 (group2)
        cp16(sbase + W1H + off, g_W1img + 36864 + off);
    CP_COMMIT();
    epilogue_h(acc1, s_src, sm + HH, 0, g, t, wm, wn);
    CP_WAIT(1);           // W2 chunk0 landed (group2 pending)
    __syncthreads();      // hbuf coherent + W2 visible to all

    // ---- GEMM2 chunk 0 (k 0..127), 2-term ----
    gemm2t<8, 272>(sm + HH, sm + W2H, sm + W2L, acc2, g, t, wm, wn);
    __syncthreads();                                    // done reading W2 buf + hbuf
    for (int off = tid * 16; off < 69632; off += 4096)  // prefetch W2 chunk1 (group3)
        cp16(sbase + W2H + off, g_W2img + 69632 + off);
    CP_COMMIT();
    CP_WAIT(1);           // W1 pass1 landed (group3 pending)
    __syncthreads();

    // ---- GEMM1 pass 1 (hid 128..255) ----
#pragma unroll
    for (int i = 0; i < 2; i++)
#pragma unroll
        for (int j = 0; j < 8; j++)
#pragma unroll
            for (int k = 0; k < 4; k++) acc1[i][j][k] = 0.f;
    gemm3<4, 144>(sm + EAH, sm + EAL, sm + W1H, sm + W1L, acc1, g, t, wm, wn);
    __syncthreads();
    epilogue_h(acc1, s_src, sm + HH, 1, g, t, wm, wn);
    CP_WAIT(0);           // W2 chunk1 landed
    __syncthreads();

    // ---- GEMM2 chunk 1 (k 128..255), 2-term ----
    gemm2t<8, 272>(sm + HH, sm + W2H, sm + W2L, acc2, g, t, wm, wn);

    // ---- epilogue: + b2, atomic scatter ----
#pragma unroll
    for (int mt = 0; mt < 2; mt++)
#pragma unroll
        for (int half = 0; half < 2; half++) {
            int r = wm * 32 + mt * 16 + g + half * 8;
            float* orow = out + (size_t)s_dst[r] * OUT_DIM;
#pragma unroll
            for (int nt = 0; nt < 8; nt++) {
                int c = wn * 64 + nt * 8 + t * 2;
                atomicAdd(orow + c,     acc2[mt][nt][half * 2 + 0] + s_b2[c]);
                atomicAdd(orow + c + 1, acc2[mt][nt][half * 2 + 1] + s_b2[c + 1]);
            }
        }
}

// =============================================================================
extern "C" void kernel_launch(void* const* d_in, const int* in_sizes, int n_in,
                              void* d_out, int out_size)
{
    const float* x  = (const float*)d_in[0];
    const void*  ei = d_in[1];
    const float* ea = (const float*)d_in[2];
    const float* W1 = (const float*)d_in[3];
    const float* b1 = (const float*)d_in[4];
    const float* W2 = (const float*)d_in[5];
    const float* b2 = (const float*)d_in[6];
    float*       out = (float*)d_out;

    const int E       = in_sizes[2] / EDGE_DIM;   // 640000
    const int n_nodes = in_sizes[0] / IN_DIM;     // 10000

    int zblk = (out_size + 255) / 256;
    if (zblk > 2960) zblk = 2960;
    zero_out_kernel<<<zblk, 256>>>(out, out_size);

    decode_edges<<<592, 256>>>(ei, E, n_nodes);
    split_weights<<<(OUT_DIM * HID + 255) / 256, 256>>>(W1, W2);

    dim3 gx((n_nodes + 127) / 128, HID / 128);
    xh_gemm<<<gx, 256>>>(x, W1, b1, n_nodes);

    cudaFuncSetAttribute(gine_fused, cudaFuncAttributeMaxDynamicSharedMemorySize, SMEM_DYN);
    gine_fused<<<E / 128, 256, SMEM_DYN>>>(ea, b2, out);
}